// round 2
// baseline (speedup 1.0000x reference)
#include <cuda_runtime.h>
#include <cstdint>

#define S_LEN 2048
#define NB 2
#define DM 1024
#define NH 16
#define DKH 64
#define BH (NB * NH)

// Scratch (allocation-free rule: __device__ globals).
__device__ float g_Q[NB * NH * S_LEN * DKH];
__device__ float g_K[NB * NH * S_LEN * DKH];
__device__ float g_V[NB * NH * S_LEN * DKH];
__device__ float g_ctx[NB * S_LEN * DM];

// ---------------------------------------------------------------------------
// tf32 helpers: 3xTF32 split (hi = tf32(x), lo = tf32(x - hi)) and mma wrapper
// ---------------------------------------------------------------------------
__device__ __forceinline__ void split32(float x, uint32_t& hi, uint32_t& lo)
{
    uint32_t h;
    asm("cvt.rna.tf32.f32 %0, %1;" : "=r"(h) : "f"(x));
    float r = x - __uint_as_float(h);
    uint32_t l;
    asm("cvt.rna.tf32.f32 %0, %1;" : "=r"(l) : "f"(r));
    hi = h; lo = l;
}

__device__ __forceinline__ void mma8(float* c, uint32_t a0, uint32_t a1,
                                     uint32_t a2, uint32_t a3,
                                     uint32_t b0, uint32_t b1)
{
    asm volatile(
        "mma.sync.aligned.m16n8k8.row.col.f32.tf32.tf32.f32 "
        "{%0,%1,%2,%3}, {%4,%5,%6,%7}, {%8,%9}, {%0,%1,%2,%3};"
        : "+f"(c[0]), "+f"(c[1]), "+f"(c[2]), "+f"(c[3])
        : "r"(a0), "r"(a1), "r"(a2), "r"(a3), "r"(b0), "r"(b1));
}

// ---------------------------------------------------------------------------
// Projection GEMM (tensor cores, 3xTF32):
//   C[4096,1024] = A[4096,1024] @ B[1024,1024] + bias
// MODE 0/1/2: scatter to g_Q/g_K/g_V in [B,H,S,dk] layout (MODE 0 also *0.125)
// MODE 3:     A := g_ctx, write flat to C
// BM=BN=128, BK=16, 8 warps, warp tile 64x32
// ---------------------------------------------------------------------------
template <int MODE>
__global__ __launch_bounds__(256) void proj_tc(
    const float* __restrict__ A, const float* __restrict__ B,
    const float* __restrict__ bias, float* __restrict__ C)
{
    __shared__ uint32_t Ah[16][132], Al[16][132], Bh[16][132], Bl[16][132];
    const float* Ap = (MODE == 3) ? (const float*)g_ctx : A;

    int tid = threadIdx.x;
    int lane = tid & 31, warp = tid >> 5;
    int g = lane >> 2, t4 = lane & 3;
    int wm = (warp & 1) * 64, wn = (warp >> 1) * 32;
    int row0 = blockIdx.y * 128, col0 = blockIdx.x * 128;

    float acc[4][4][4];
#pragma unroll
    for (int i = 0; i < 4; i++)
#pragma unroll
        for (int j = 0; j < 4; j++)
#pragma unroll
            for (int q = 0; q < 4; q++) acc[i][j][q] = 0.f;

    for (int k0 = 0; k0 < DM; k0 += 16) {
        // A tile fill: 128 rows x 16 k
#pragma unroll
        for (int i = 0; i < 2; i++) {
            int lin = tid + i * 256;
            int r = lin >> 2, kq = (lin & 3) * 4;
            float4 v = *(const float4*)(Ap + (size_t)(row0 + r) * DM + k0 + kq);
            uint32_t h, l;
            split32(v.x, h, l); Ah[kq + 0][r] = h; Al[kq + 0][r] = l;
            split32(v.y, h, l); Ah[kq + 1][r] = h; Al[kq + 1][r] = l;
            split32(v.z, h, l); Ah[kq + 2][r] = h; Al[kq + 2][r] = l;
            split32(v.w, h, l); Ah[kq + 3][r] = h; Al[kq + 3][r] = l;
        }
        // B tile fill: 16 k x 128 n (B row-major [k][n])
#pragma unroll
        for (int i = 0; i < 2; i++) {
            int lin = tid + i * 256;
            int kr = lin >> 5, nq = (lin & 31) * 4;
            float4 v = *(const float4*)(B + (size_t)(k0 + kr) * DM + col0 + nq);
            uint32_t h, l;
            split32(v.x, h, l); Bh[kr][nq + 0] = h; Bl[kr][nq + 0] = l;
            split32(v.y, h, l); Bh[kr][nq + 1] = h; Bl[kr][nq + 1] = l;
            split32(v.z, h, l); Bh[kr][nq + 2] = h; Bl[kr][nq + 2] = l;
            split32(v.w, h, l); Bh[kr][nq + 3] = h; Bl[kr][nq + 3] = l;
        }
        __syncthreads();
#pragma unroll
        for (int ks = 0; ks < 2; ks++) {
            int kb = ks * 8;
            uint32_t ah[4][4], al_[4][4], bh[4][2], bl[4][2];
#pragma unroll
            for (int mf = 0; mf < 4; mf++) {
                int m = wm + mf * 16;
                ah[mf][0] = Ah[kb + t4][m + g];     al_[mf][0] = Al[kb + t4][m + g];
                ah[mf][1] = Ah[kb + t4][m + g + 8]; al_[mf][1] = Al[kb + t4][m + g + 8];
                ah[mf][2] = Ah[kb + t4 + 4][m + g];     al_[mf][2] = Al[kb + t4 + 4][m + g];
                ah[mf][3] = Ah[kb + t4 + 4][m + g + 8]; al_[mf][3] = Al[kb + t4 + 4][m + g + 8];
            }
#pragma unroll
            for (int nf = 0; nf < 4; nf++) {
                int n = wn + nf * 8;
                bh[nf][0] = Bh[kb + t4][n + g];     bl[nf][0] = Bl[kb + t4][n + g];
                bh[nf][1] = Bh[kb + t4 + 4][n + g]; bl[nf][1] = Bl[kb + t4 + 4][n + g];
            }
#pragma unroll
            for (int mf = 0; mf < 4; mf++)
#pragma unroll
                for (int nf = 0; nf < 4; nf++) {
                    mma8(acc[mf][nf], ah[mf][0], ah[mf][1], ah[mf][2], ah[mf][3],
                         bh[nf][0], bh[nf][1]);
                    mma8(acc[mf][nf], ah[mf][0], ah[mf][1], ah[mf][2], ah[mf][3],
                         bl[nf][0], bl[nf][1]);
                    mma8(acc[mf][nf], al_[mf][0], al_[mf][1], al_[mf][2], al_[mf][3],
                         bh[nf][0], bh[nf][1]);
                }
        }
        __syncthreads();
    }

#pragma unroll
    for (int mf = 0; mf < 4; mf++)
#pragma unroll
        for (int nf = 0; nf < 4; nf++) {
            int r = row0 + wm + mf * 16 + g;
            int c = col0 + wn + nf * 8 + 2 * t4;
            float b0 = bias[c], b1 = bias[c + 1];
            float v00 = acc[mf][nf][0] + b0, v01 = acc[mf][nf][1] + b1;
            float v10 = acc[mf][nf][2] + b0, v11 = acc[mf][nf][3] + b1;
            if (MODE == 0) { v00 *= 0.125f; v01 *= 0.125f; v10 *= 0.125f; v11 *= 0.125f; }
            if (MODE == 3) {
                *(float2*)&C[(size_t)r * DM + c] = make_float2(v00, v01);
                *(float2*)&C[(size_t)(r + 8) * DM + c] = make_float2(v10, v11);
            } else {
                float* dst = (MODE == 0) ? g_Q : (MODE == 1) ? g_K : g_V;
                int h = c >> 6, d = c & 63;
                int b = r >> 11, s = r & 2047;
                size_t base = (((size_t)(b << 4) + h) * S_LEN) * DKH + d;
                *(float2*)&dst[base + (size_t)s * DKH] = make_float2(v00, v01);
                *(float2*)&dst[base + (size_t)(s + 8) * DKH] = make_float2(v10, v11);
            }
        }
}

// ---------------------------------------------------------------------------
// scores[bh] = Qh @ Kh^T  (Q pre-scaled by 1/8). Per head [2048,64]x[64,2048].
// BM=BN=128, BK=16, warp tile 64x32
// ---------------------------------------------------------------------------
__global__ __launch_bounds__(256) void scores_tc(float* __restrict__ W)
{
    __shared__ uint32_t Ah[16][132], Al[16][132], Bh[16][132], Bl[16][132];
    int bh = blockIdx.z;
    const float* Qh = g_Q + (size_t)bh * S_LEN * DKH;
    const float* Kh = g_K + (size_t)bh * S_LEN * DKH;
    float* Wh = W + (size_t)bh * S_LEN * S_LEN;

    int tid = threadIdx.x;
    int lane = tid & 31, warp = tid >> 5;
    int g = lane >> 2, t4 = lane & 3;
    int wm = (warp & 1) * 64, wn = (warp >> 1) * 32;
    int row0 = blockIdx.y * 128, col0 = blockIdx.x * 128;

    float acc[4][4][4];
#pragma unroll
    for (int i = 0; i < 4; i++)
#pragma unroll
        for (int j = 0; j < 4; j++)
#pragma unroll
            for (int q = 0; q < 4; q++) acc[i][j][q] = 0.f;

    for (int k0 = 0; k0 < DKH; k0 += 16) {
#pragma unroll
        for (int i = 0; i < 2; i++) {
            int lin = tid + i * 256;
            int r = lin >> 2, kq = (lin & 3) * 4;
            float4 v = *(const float4*)(Qh + (size_t)(row0 + r) * DKH + k0 + kq);
            uint32_t h, l;
            split32(v.x, h, l); Ah[kq + 0][r] = h; Al[kq + 0][r] = l;
            split32(v.y, h, l); Ah[kq + 1][r] = h; Al[kq + 1][r] = l;
            split32(v.z, h, l); Ah[kq + 2][r] = h; Al[kq + 2][r] = l;
            split32(v.w, h, l); Ah[kq + 3][r] = h; Al[kq + 3][r] = l;
        }
        // B = Kh^T: load Kh rows (n), scatter into Bs[k][n]
#pragma unroll
        for (int i = 0; i < 2; i++) {
            int lin = tid + i * 256;
            int n = lin >> 2, kq = (lin & 3) * 4;
            float4 v = *(const float4*)(Kh + (size_t)(col0 + n) * DKH + k0 + kq);
            uint32_t h, l;
            split32(v.x, h, l); Bh[kq + 0][n] = h; Bl[kq + 0][n] = l;
            split32(v.y, h, l); Bh[kq + 1][n] = h; Bl[kq + 1][n] = l;
            split32(v.z, h, l); Bh[kq + 2][n] = h; Bl[kq + 2][n] = l;
            split32(v.w, h, l); Bh[kq + 3][n] = h; Bl[kq + 3][n] = l;
        }
        __syncthreads();
#pragma unroll
        for (int ks = 0; ks < 2; ks++) {
            int kb = ks * 8;
            uint32_t ah[4][4], al_[4][4], bh[4][2], bl[4][2];
#pragma unroll
            for (int mf = 0; mf < 4; mf++) {
                int m = wm + mf * 16;
                ah[mf][0] = Ah[kb + t4][m + g];     al_[mf][0] = Al[kb + t4][m + g];
                ah[mf][1] = Ah[kb + t4][m + g + 8]; al_[mf][1] = Al[kb + t4][m + g + 8];
                ah[mf][2] = Ah[kb + t4 + 4][m + g];     al_[mf][2] = Al[kb + t4 + 4][m + g];
                ah[mf][3] = Ah[kb + t4 + 4][m + g + 8]; al_[mf][3] = Al[kb + t4 + 4][m + g + 8];
            }
#pragma unroll
            for (int nf = 0; nf < 4; nf++) {
                int n = wn + nf * 8;
                bh[nf][0] = Bh[kb + t4][n + g];     bl[nf][0] = Bl[kb + t4][n + g];
                bh[nf][1] = Bh[kb + t4 + 4][n + g]; bl[nf][1] = Bl[kb + t4 + 4][n + g];
            }
#pragma unroll
            for (int mf = 0; mf < 4; mf++)
#pragma unroll
                for (int nf = 0; nf < 4; nf++) {
                    mma8(acc[mf][nf], ah[mf][0], ah[mf][1], ah[mf][2], ah[mf][3],
                         bh[nf][0], bh[nf][1]);
                    mma8(acc[mf][nf], ah[mf][0], ah[mf][1], ah[mf][2], ah[mf][3],
                         bl[nf][0], bl[nf][1]);
                    mma8(acc[mf][nf], al_[mf][0], al_[mf][1], al_[mf][2], al_[mf][3],
                         bh[nf][0], bh[nf][1]);
                }
        }
        __syncthreads();
    }

#pragma unroll
    for (int mf = 0; mf < 4; mf++)
#pragma unroll
        for (int nf = 0; nf < 4; nf++) {
            int r = row0 + wm + mf * 16 + g;
            int c = col0 + wn + nf * 8 + 2 * t4;
            *(float2*)&Wh[(size_t)r * S_LEN + c] =
                make_float2(acc[mf][nf][0], acc[mf][nf][1]);
            *(float2*)&Wh[(size_t)(r + 8) * S_LEN + c] =
                make_float2(acc[mf][nf][2], acc[mf][nf][3]);
        }
}

// ---------------------------------------------------------------------------
// In-place row softmax over 2048 cols. One block (256 thr) per row, float4.
// ---------------------------------------------------------------------------
__global__ __launch_bounds__(256) void softmax_kernel(float* __restrict__ W)
{
    __shared__ float red[256];
    float4* p = (float4*)(W + (size_t)blockIdx.x * S_LEN);
    int tid = threadIdx.x;
    float4 v0 = p[tid], v1 = p[tid + 256];
    float m = fmaxf(fmaxf(fmaxf(v0.x, v0.y), fmaxf(v0.z, v0.w)),
                    fmaxf(fmaxf(v1.x, v1.y), fmaxf(v1.z, v1.w)));
    red[tid] = m;
    __syncthreads();
    for (int s = 128; s > 0; s >>= 1) {
        if (tid < s) red[tid] = fmaxf(red[tid], red[tid + s]);
        __syncthreads();
    }
    m = red[0];
    __syncthreads();
    v0.x = __expf(v0.x - m); v0.y = __expf(v0.y - m);
    v0.z = __expf(v0.z - m); v0.w = __expf(v0.w - m);
    v1.x = __expf(v1.x - m); v1.y = __expf(v1.y - m);
    v1.z = __expf(v1.z - m); v1.w = __expf(v1.w - m);
    red[tid] = (v0.x + v0.y + v0.z + v0.w) + (v1.x + v1.y + v1.z + v1.w);
    __syncthreads();
    for (int s = 128; s > 0; s >>= 1) {
        if (tid < s) red[tid] += red[tid + s];
        __syncthreads();
    }
    float inv = 1.0f / red[0];
    v0.x *= inv; v0.y *= inv; v0.z *= inv; v0.w *= inv;
    v1.x *= inv; v1.y *= inv; v1.z *= inv; v1.w *= inv;
    p[tid] = v0; p[tid + 256] = v1;
}

// ---------------------------------------------------------------------------
// context[bh] = W_h[2048,2048] @ V_h[2048,64] -> g_ctx in [B,S,D] layout
// BM=128, BN=64, BK=16, warp tile 32x32
// ---------------------------------------------------------------------------
__global__ __launch_bounds__(256) void context_tc(const float* __restrict__ W)
{
    __shared__ uint32_t Ah[16][132], Al[16][132], Bh[16][68], Bl[16][68];
    int bh = blockIdx.z;
    const float* Wh = W + (size_t)bh * S_LEN * S_LEN;
    const float* Vh = g_V + (size_t)bh * S_LEN * DKH;
    int b = bh >> 4, h = bh & 15;

    int tid = threadIdx.x;
    int lane = tid & 31, warp = tid >> 5;
    int g = lane >> 2, t4 = lane & 3;
    int wm = (warp >> 1) * 32, wn = (warp & 1) * 32;
    int row0 = blockIdx.y * 128;

    float acc[2][4][4];
#pragma unroll
    for (int i = 0; i < 2; i++)
#pragma unroll
        for (int j = 0; j < 4; j++)
#pragma unroll
            for (int q = 0; q < 4; q++) acc[i][j][q] = 0.f;

    for (int k0 = 0; k0 < S_LEN; k0 += 16) {
#pragma unroll
        for (int i = 0; i < 2; i++) {
            int lin = tid + i * 256;
            int r = lin >> 2, kq = (lin & 3) * 4;
            float4 v = *(const float4*)(Wh + (size_t)(row0 + r) * S_LEN + k0 + kq);
            uint32_t hh, l;
            split32(v.x, hh, l); Ah[kq + 0][r] = hh; Al[kq + 0][r] = l;
            split32(v.y, hh, l); Ah[kq + 1][r] = hh; Al[kq + 1][r] = l;
            split32(v.z, hh, l); Ah[kq + 2][r] = hh; Al[kq + 2][r] = l;
            split32(v.w, hh, l); Ah[kq + 3][r] = hh; Al[kq + 3][r] = l;
        }
        {
            int lin = tid;            // 256 float4 = 16k x 64n
            int kr = lin >> 4, nq = (lin & 15) * 4;
            float4 v = *(const float4*)(Vh + (size_t)(k0 + kr) * DKH + nq);
            uint32_t hh, l;
            split32(v.x, hh, l); Bh[kr][nq + 0] = hh; Bl[kr][nq + 0] = l;
            split32(v.y, hh, l); Bh[kr][nq + 1] = hh; Bl[kr][nq + 1] = l;
            split32(v.z, hh, l); Bh[kr][nq + 2] = hh; Bl[kr][nq + 2] = l;
            split32(v.w, hh, l); Bh[kr][nq + 3] = hh; Bl[kr][nq + 3] = l;
        }
        __syncthreads();
#pragma unroll
        for (int ks = 0; ks < 2; ks++) {
            int kb = ks * 8;
            uint32_t ah[2][4], al_[2][4], bh[4][2], bl[4][2];
#pragma unroll
            for (int mf = 0; mf < 2; mf++) {
                int m = wm + mf * 16;
                ah[mf][0] = Ah[kb + t4][m + g];     al_[mf][0] = Al[kb + t4][m + g];
                ah[mf][1] = Ah[kb + t4][m + g + 8]; al_[mf][1] = Al[kb + t4][m + g + 8];
                ah[mf][2] = Ah[kb + t4 + 4][m + g];     al_[mf][2] = Al[kb + t4 + 4][m + g];
                ah[mf][3] = Ah[kb + t4 + 4][m + g + 8]; al_[mf][3] = Al[kb + t4 + 4][m + g + 8];
            }
#pragma unroll
            for (int nf = 0; nf < 4; nf++) {
                int n = wn + nf * 8;
                bh[nf][0] = Bh[kb + t4][n + g];     bl[nf][0] = Bl[kb + t4][n + g];
                bh[nf][1] = Bh[kb + t4 + 4][n + g]; bl[nf][1] = Bl[kb + t4 + 4][n + g];
            }
#pragma unroll
            for (int mf = 0; mf < 2; mf++)
#pragma unroll
                for (int nf = 0; nf < 4; nf++) {
                    mma8(acc[mf][nf], ah[mf][0], ah[mf][1], ah[mf][2], ah[mf][3],
                         bh[nf][0], bh[nf][1]);
                    mma8(acc[mf][nf], ah[mf][0], ah[mf][1], ah[mf][2], ah[mf][3],
                         bl[nf][0], bl[nf][1]);
                    mma8(acc[mf][nf], al_[mf][0], al_[mf][1], al_[mf][2], al_[mf][3],
                         bh[nf][0], bh[nf][1]);
                }
        }
        __syncthreads();
    }

#pragma unroll
    for (int mf = 0; mf < 2; mf++)
#pragma unroll
        for (int nf = 0; nf < 4; nf++) {
            int r = row0 + wm + mf * 16 + g;
            int c = wn + nf * 8 + 2 * t4;
            size_t base = ((size_t)b * S_LEN) * DM + (size_t)h * DKH + c;
            *(float2*)&g_ctx[base + (size_t)r * DM] =
                make_float2(acc[mf][nf][0], acc[mf][nf][1]);
            *(float2*)&g_ctx[base + (size_t)(r + 8) * DM] =
                make_float2(acc[mf][nf][2], acc[mf][nf][3]);
        }
}

// ---------------------------------------------------------------------------
extern "C" void kernel_launch(void* const* d_in, const int* in_sizes, int n_in,
                              void* d_out, int out_size)
{
    const float* query = (const float*)d_in[0];
    const float* key_  = (const float*)d_in[1];
    const float* value = (const float*)d_in[2];
    const float* Wq = (const float*)d_in[3];
    const float* bq = (const float*)d_in[4];
    const float* Wk = (const float*)d_in[5];
    const float* bk = (const float*)d_in[6];
    const float* Wv = (const float*)d_in[7];
    const float* bv = (const float*)d_in[8];
    const float* Wo = (const float*)d_in[9];
    const float* bo = (const float*)d_in[10];

    float* out = (float*)d_out;                                  // [2,2048,1024]
    float* weights = out + (size_t)NB * S_LEN * DM;              // [2,16,2048,2048]

    dim3 blk(256);
    dim3 gProj(DM / 128, (NB * S_LEN) / 128);                    // (8, 32)
    proj_tc<0><<<gProj, blk>>>(query, Wq, bq, nullptr);
    proj_tc<1><<<gProj, blk>>>(key_,  Wk, bk, nullptr);
    proj_tc<2><<<gProj, blk>>>(value, Wv, bv, nullptr);

    dim3 gScore(S_LEN / 128, S_LEN / 128, BH);                   // (16, 16, 32)
    scores_tc<<<gScore, blk>>>(weights);

    softmax_kernel<<<BH * S_LEN, blk>>>(weights);                // 65536 rows

    dim3 gCtx(1, S_LEN / 128, BH);                               // (1, 16, 32)
    context_tc<<<gCtx, blk>>>(weights);

    proj_tc<3><<<gProj, blk>>>(nullptr, Wo, bo, out);
}

// round 4
// speedup vs baseline: 1.8953x; 1.8953x over previous
#include <cuda_runtime.h>
#include <cstdint>

#define S_LEN 2048
#define NB 2
#define DM 1024
#define NH 16
#define DKH 64
#define BH (NB * NH)

// Scratch (allocation-free rule: __device__ globals).
__device__ float g_Q[NB * NH * S_LEN * DKH];
__device__ float g_K[NB * NH * S_LEN * DKH];
__device__ float g_V[NB * NH * S_LEN * DKH];
__device__ float g_ctx[NB * S_LEN * DM];

// ---------------------------------------------------------------------------
// tf32 helpers
// ---------------------------------------------------------------------------
__device__ __forceinline__ uint32_t cvt_tf32(float x)
{
    uint32_t r;
    asm("cvt.rna.tf32.f32 %0, %1;" : "=r"(r) : "f"(x));
    return r;
}

__device__ __forceinline__ void split32(float x, uint32_t& hi, uint32_t& lo)
{
    hi = cvt_tf32(x);
    lo = cvt_tf32(x - __uint_as_float(hi));
}

__device__ __forceinline__ void mma8(float* c, const uint32_t* a,
                                     uint32_t b0, uint32_t b1)
{
    asm volatile(
        "mma.sync.aligned.m16n8k8.row.col.f32.tf32.tf32.f32 "
        "{%0,%1,%2,%3}, {%4,%5,%6,%7}, {%8,%9}, {%0,%1,%2,%3};"
        : "+f"(c[0]), "+f"(c[1]), "+f"(c[2]), "+f"(c[3])
        : "r"(a[0]), "r"(a[1]), "r"(a[2]), "r"(a[3]), "r"(b0), "r"(b1));
}

__device__ __forceinline__ void ldsm4(uint32_t* r, uint32_t addr)
{
    asm volatile(
        "ldmatrix.sync.aligned.m8n8.x4.shared.b16 {%0,%1,%2,%3}, [%4];"
        : "=r"(r[0]), "=r"(r[1]), "=r"(r[2]), "=r"(r[3]) : "r"(addr));
}

__device__ __forceinline__ void sts128(uint32_t addr, uint32_t a, uint32_t b,
                                       uint32_t c, uint32_t d)
{
    asm volatile("st.shared.v4.b32 [%0], {%1,%2,%3,%4};"
                 :: "r"(addr), "r"(a), "r"(b), "r"(c), "r"(d));
}

// ---------------------------------------------------------------------------
// smem tile layout: row r = 128 bytes = 8 chunks of 16B.
//   chunks 0-3: hi tf32 for k 0..15 ; chunks 4-7: lo tf32.
//   physical chunk = logical chunk ^ (r & 7)   (conflict-free STS.128 + LDSM)
// ---------------------------------------------------------------------------

// Fill from row-major source (k contiguous): rows=128, BK=16. src pre-offset
// to (row0, k0); ld in floats.
__device__ __forceinline__ void fill_rowmajor(uint32_t sbase,
                                              const float* __restrict__ src,
                                              int ld)
{
    int tid = threadIdx.x;
#pragma unroll
    for (int i = 0; i < 2; i++) {
        int lin = tid + i * 256;
        int m = lin >> 2, q = lin & 3;
        float4 v = *(const float4*)(src + (size_t)m * ld + q * 4);
        uint32_t h0, l0, h1, l1, h2, l2, h3, l3;
        split32(v.x, h0, l0); split32(v.y, h1, l1);
        split32(v.z, h2, l2); split32(v.w, h3, l3);
        uint32_t row = sbase + m * 128;
        sts128(row + (((q) ^ (m & 7)) << 4), h0, h1, h2, h3);
        sts128(row + (((q + 4) ^ (m & 7)) << 4), l0, l1, l2, l3);
    }
}

// Fill B[n][k] from a [k][n] row-major source (proj weights, V).
// Each thread: one n, one k-quad via 4 coalesced strided loads.
// NW = 128 or 64. src pre-offset to (k0, col0); ld in floats.
template <int NW>
__device__ __forceinline__ void fill_kmajor(uint32_t sbase,
                                            const float* __restrict__ src,
                                            int ld)
{
    int tid = threadIdx.x;
#pragma unroll
    for (int i = 0; i < NW / 64; i++) {
        int lin = tid + i * 256;
        int n = lin & (NW - 1);
        int q = (NW == 128) ? (lin >> 7) : (lin >> 6);
        float x0 = src[(size_t)(q * 4 + 0) * ld + n];
        float x1 = src[(size_t)(q * 4 + 1) * ld + n];
        float x2 = src[(size_t)(q * 4 + 2) * ld + n];
        float x3 = src[(size_t)(q * 4 + 3) * ld + n];
        uint32_t h0, l0, h1, l1, h2, l2, h3, l3;
        split32(x0, h0, l0); split32(x1, h1, l1);
        split32(x2, h2, l2); split32(x3, h3, l3);
        uint32_t row = sbase + n * 128;
        sts128(row + (((q) ^ (n & 7)) << 4), h0, h1, h2, h3);
        sts128(row + (((q + 4) ^ (n & 7)) << 4), l0, l1, l2, l3);
    }
}

// ---------------------------------------------------------------------------
// Projection GEMM: C[4096,1024] = A @ B + bias (3xTF32, ldmatrix)
// MODE 0/1/2: scatter to g_Q/g_K/g_V in [B,H,S,dk] (MODE 0 also *0.125)
// MODE 3:     A := g_ctx, write flat to C
// BM=BN=128, BK=16, 8 warps, warp tile 64x32
// ---------------------------------------------------------------------------
template <int MODE>
__global__ __launch_bounds__(256) void proj_tc(
    const float* __restrict__ A, const float* __restrict__ B,
    const float* __restrict__ bias, float* __restrict__ C)
{
    __shared__ uint32_t sA[128 * 32], sB[128 * 32];
    const float* Ap = (MODE == 3) ? (const float*)g_ctx : A;
    uint32_t sa = (uint32_t)__cvta_generic_to_shared(sA);
    uint32_t sb = (uint32_t)__cvta_generic_to_shared(sB);

    int tid = threadIdx.x;
    int lane = tid & 31, warp = tid >> 5;
    int g = lane >> 2, t4 = lane & 3;
    int mat = lane >> 3, rl = lane & 7;
    int wm = (warp & 1) * 64, wn = (warp >> 1) * 32;
    int row0 = blockIdx.y * 128, col0 = blockIdx.x * 128;

    int rowA = wm + (mat & 1) * 8 + rl;
    uint32_t aBase = sa + rowA * 128 + ((rowA & 7) << 4);
    int aSel = mat >> 1;
    int rowB = wn + (mat >> 1) * 8 + rl;
    uint32_t bBase = sb + rowB * 128 + ((rowB & 7) << 4);
    int bSel = mat & 1;

    float acc[4][4][4];
#pragma unroll
    for (int i = 0; i < 4; i++)
#pragma unroll
        for (int j = 0; j < 4; j++)
#pragma unroll
            for (int q = 0; q < 4; q++) acc[i][j][q] = 0.f;

    for (int k0 = 0; k0 < DM; k0 += 16) {
        fill_rowmajor(sa, Ap + (size_t)row0 * DM + k0, DM);
        fill_kmajor<128>(sb, B + (size_t)k0 * DM + col0, DM);
        __syncthreads();
#pragma unroll
        for (int ks = 0; ks < 2; ks++) {
            int lc = ks * 2;
            uint32_t ah[4][4], al[4][4], bh[2][4], bl[2][4];
            uint32_t axh = (uint32_t)(lc + aSel) << 4;
            uint32_t axl = (uint32_t)(lc + aSel + 4) << 4;
#pragma unroll
            for (int mf = 0; mf < 4; mf++) {
                ldsm4(ah[mf], (aBase + mf * 2048) ^ axh);
                ldsm4(al[mf], (aBase + mf * 2048) ^ axl);
            }
            uint32_t bxh = (uint32_t)(lc + bSel) << 4;
            uint32_t bxl = (uint32_t)(lc + bSel + 4) << 4;
#pragma unroll
            for (int p = 0; p < 2; p++) {
                ldsm4(bh[p], (bBase + p * 2048) ^ bxh);
                ldsm4(bl[p], (bBase + p * 2048) ^ bxl);
            }
#pragma unroll
            for (int mf = 0; mf < 4; mf++)
#pragma unroll
                for (int nf = 0; nf < 4; nf++) {
                    int p = nf >> 1, o = (nf & 1) * 2;
                    mma8(acc[mf][nf], ah[mf], bh[p][o], bh[p][o + 1]);
                    mma8(acc[mf][nf], ah[mf], bl[p][o], bl[p][o + 1]);
                    mma8(acc[mf][nf], al[mf], bh[p][o], bh[p][o + 1]);
                }
        }
        __syncthreads();
    }

#pragma unroll
    for (int mf = 0; mf < 4; mf++)
#pragma unroll
        for (int nf = 0; nf < 4; nf++) {
            int r = row0 + wm + mf * 16 + g;
            int c = col0 + wn + nf * 8 + 2 * t4;
            float b0 = bias[c], b1 = bias[c + 1];
            float v00 = acc[mf][nf][0] + b0, v01 = acc[mf][nf][1] + b1;
            float v10 = acc[mf][nf][2] + b0, v11 = acc[mf][nf][3] + b1;
            if (MODE == 0) { v00 *= 0.125f; v01 *= 0.125f; v10 *= 0.125f; v11 *= 0.125f; }
            if (MODE == 3) {
                *(float2*)&C[(size_t)r * DM + c] = make_float2(v00, v01);
                *(float2*)&C[(size_t)(r + 8) * DM + c] = make_float2(v10, v11);
            } else {
                float* dst = (MODE == 0) ? g_Q : (MODE == 1) ? g_K : g_V;
                int h = c >> 6, d = c & 63;
                int b = r >> 11, s = r & 2047;
                size_t base = (((size_t)(b << 4) + h) * S_LEN) * DKH + d;
                *(float2*)&dst[base + (size_t)s * DKH] = make_float2(v00, v01);
                *(float2*)&dst[base + (size_t)(s + 8) * DKH] = make_float2(v10, v11);
            }
        }
}

// ---------------------------------------------------------------------------
// scores[bh] = Qh @ Kh^T (Q pre-scaled). [2048,64]x[64,2048] per head.
// BM=BN=128, BK=16, warp tile 64x32
// ---------------------------------------------------------------------------
__global__ __launch_bounds__(256) void scores_tc(float* __restrict__ W)
{
    __shared__ uint32_t sA[128 * 32], sB[128 * 32];
    uint32_t sa = (uint32_t)__cvta_generic_to_shared(sA);
    uint32_t sb = (uint32_t)__cvta_generic_to_shared(sB);
    int bh = blockIdx.z;
    const float* Qh = g_Q + (size_t)bh * S_LEN * DKH;
    const float* Kh = g_K + (size_t)bh * S_LEN * DKH;
    float* Wh = W + (size_t)bh * S_LEN * S_LEN;

    int tid = threadIdx.x;
    int lane = tid & 31, warp = tid >> 5;
    int g = lane >> 2, t4 = lane & 3;
    int mat = lane >> 3, rl = lane & 7;
    int wm = (warp & 1) * 64, wn = (warp >> 1) * 32;
    int row0 = blockIdx.y * 128, col0 = blockIdx.x * 128;

    int rowA = wm + (mat & 1) * 8 + rl;
    uint32_t aBase = sa + rowA * 128 + ((rowA & 7) << 4);
    int aSel = mat >> 1;
    int rowB = wn + (mat >> 1) * 8 + rl;
    uint32_t bBase = sb + rowB * 128 + ((rowB & 7) << 4);
    int bSel = mat & 1;

    float acc[4][4][4];
#pragma unroll
    for (int i = 0; i < 4; i++)
#pragma unroll
        for (int j = 0; j < 4; j++)
#pragma unroll
            for (int q = 0; q < 4; q++) acc[i][j][q] = 0.f;

#pragma unroll
    for (int k0 = 0; k0 < DKH; k0 += 16) {
        fill_rowmajor(sa, Qh + (size_t)row0 * DKH + k0, DKH);
        fill_rowmajor(sb, Kh + (size_t)col0 * DKH + k0, DKH);
        __syncthreads();
#pragma unroll
        for (int ks = 0; ks < 2; ks++) {
            int lc = ks * 2;
            uint32_t ah[4][4], al[4][4], bh[2][4], bl[2][4];
            uint32_t axh = (uint32_t)(lc + aSel) << 4;
            uint32_t axl = (uint32_t)(lc + aSel + 4) << 4;
#pragma unroll
            for (int mf = 0; mf < 4; mf++) {
                ldsm4(ah[mf], (aBase + mf * 2048) ^ axh);
                ldsm4(al[mf], (aBase + mf * 2048) ^ axl);
            }
            uint32_t bxh = (uint32_t)(lc + bSel) << 4;
            uint32_t bxl = (uint32_t)(lc + bSel + 4) << 4;
#pragma unroll
            for (int p = 0; p < 2; p++) {
                ldsm4(bh[p], (bBase + p * 2048) ^ bxh);
                ldsm4(bl[p], (bBase + p * 2048) ^ bxl);
            }
#pragma unroll
            for (int mf = 0; mf < 4; mf++)
#pragma unroll
                for (int nf = 0; nf < 4; nf++) {
                    int p = nf >> 1, o = (nf & 1) * 2;
                    mma8(acc[mf][nf], ah[mf], bh[p][o], bh[p][o + 1]);
                    mma8(acc[mf][nf], ah[mf], bl[p][o], bl[p][o + 1]);
                    mma8(acc[mf][nf], al[mf], bh[p][o], bh[p][o + 1]);
                }
        }
        __syncthreads();
    }

#pragma unroll
    for (int mf = 0; mf < 4; mf++)
#pragma unroll
        for (int nf = 0; nf < 4; nf++) {
            int r = row0 + wm + mf * 16 + g;
            int c = col0 + wn + nf * 8 + 2 * t4;
            *(float2*)&Wh[(size_t)r * S_LEN + c] =
                make_float2(acc[mf][nf][0], acc[mf][nf][1]);
            *(float2*)&Wh[(size_t)(r + 8) * S_LEN + c] =
                make_float2(acc[mf][nf][2], acc[mf][nf][3]);
        }
}

// ---------------------------------------------------------------------------
// In-place row softmax over 2048 cols. One block (256 thr) per row.
// ---------------------------------------------------------------------------
__global__ __launch_bounds__(256) void softmax_kernel(float* __restrict__ W)
{
    __shared__ float red[256];
    float4* p = (float4*)(W + (size_t)blockIdx.x * S_LEN);
    int tid = threadIdx.x;
    float4 v0 = p[tid], v1 = p[tid + 256];
    float m = fmaxf(fmaxf(fmaxf(v0.x, v0.y), fmaxf(v0.z, v0.w)),
                    fmaxf(fmaxf(v1.x, v1.y), fmaxf(v1.z, v1.w)));
    red[tid] = m;
    __syncthreads();
    for (int s = 128; s > 0; s >>= 1) {
        if (tid < s) red[tid] = fmaxf(red[tid], red[tid + s]);
        __syncthreads();
    }
    m = red[0];
    __syncthreads();
    v0.x = __expf(v0.x - m); v0.y = __expf(v0.y - m);
    v0.z = __expf(v0.z - m); v0.w = __expf(v0.w - m);
    v1.x = __expf(v1.x - m); v1.y = __expf(v1.y - m);
    v1.z = __expf(v1.z - m); v1.w = __expf(v1.w - m);
    red[tid] = (v0.x + v0.y + v0.z + v0.w) + (v1.x + v1.y + v1.z + v1.w);
    __syncthreads();
    for (int s = 128; s > 0; s >>= 1) {
        if (tid < s) red[tid] += red[tid + s];
        __syncthreads();
    }
    float inv = 1.0f / red[0];
    v0.x *= inv; v0.y *= inv; v0.z *= inv; v0.w *= inv;
    v1.x *= inv; v1.y *= inv; v1.z *= inv; v1.w *= inv;
    p[tid] = v0; p[tid + 256] = v1;
}

// ---------------------------------------------------------------------------
// context[bh] = W_h[2048,2048] @ V_h[2048,64] -> g_ctx [B,S,D]
// BM=128, BN=64, BK=16, warp tile 32x32
// ---------------------------------------------------------------------------
__global__ __launch_bounds__(256) void context_tc(const float* __restrict__ W)
{
    __shared__ uint32_t sA[128 * 32], sB[64 * 32];
    uint32_t sa = (uint32_t)__cvta_generic_to_shared(sA);
    uint32_t sb = (uint32_t)__cvta_generic_to_shared(sB);
    int bh = blockIdx.z;
    const float* Wh = W + (size_t)bh * S_LEN * S_LEN;
    const float* Vh = g_V + (size_t)bh * S_LEN * DKH;
    int b = bh >> 4, h = bh & 15;

    int tid = threadIdx.x;
    int lane = tid & 31, warp = tid >> 5;
    int g = lane >> 2, t4 = lane & 3;
    int mat = lane >> 3, rl = lane & 7;
    int wm = (warp >> 1) * 32, wn = (warp & 1) * 32;
    int row0 = blockIdx.y * 128;

    int rowA = wm + (mat & 1) * 8 + rl;
    uint32_t aBase = sa + rowA * 128 + ((rowA & 7) << 4);
    int aSel = mat >> 1;
    int rowB = wn + (mat >> 1) * 8 + rl;
    uint32_t bBase = sb + rowB * 128 + ((rowB & 7) << 4);
    int bSel = mat & 1;

    float acc[2][4][4];
#pragma unroll
    for (int i = 0; i < 2; i++)
#pragma unroll
        for (int j = 0; j < 4; j++)
#pragma unroll
            for (int q = 0; q < 4; q++) acc[i][j][q] = 0.f;

    for (int k0 = 0; k0 < S_LEN; k0 += 16) {
        fill_rowmajor(sa, Wh + (size_t)row0 * S_LEN + k0, S_LEN);
        fill_kmajor<64>(sb, Vh + (size_t)k0 * DKH, DKH);
        __syncthreads();
#pragma unroll
        for (int ks = 0; ks < 2; ks++) {
            int lc = ks * 2;
            uint32_t ah[2][4], al[2][4], bh[2][4], bl[2][4];
            uint32_t axh = (uint32_t)(lc + aSel) << 4;
            uint32_t axl = (uint32_t)(lc + aSel + 4) << 4;
#pragma unroll
            for (int mf = 0; mf < 2; mf++) {
                ldsm4(ah[mf], (aBase + mf * 2048) ^ axh);
                ldsm4(al[mf], (aBase + mf * 2048) ^ axl);
            }
            uint32_t bxh = (uint32_t)(lc + bSel) << 4;
            uint32_t bxl = (uint32_t)(lc + bSel + 4) << 4;
#pragma unroll
            for (int p = 0; p < 2; p++) {
                ldsm4(bh[p], (bBase + p * 2048) ^ bxh);
                ldsm4(bl[p], (bBase + p * 2048) ^ bxl);
            }
#pragma unroll
            for (int mf = 0; mf < 2; mf++)
#pragma unroll
                for (int nf = 0; nf < 4; nf++) {
                    int p = nf >> 1, o = (nf & 1) * 2;
                    mma8(acc[mf][nf], ah[mf], bh[p][o], bh[p][o + 1]);
                    mma8(acc[mf][nf], ah[mf], bl[p][o], bl[p][o + 1]);
                    mma8(acc[mf][nf], al[mf], bh[p][o], bh[p][o + 1]);
                }
        }
        __syncthreads();
    }

#pragma unroll
    for (int mf = 0; mf < 2; mf++)
#pragma unroll
        for (int nf = 0; nf < 4; nf++) {
            int r = row0 + wm + mf * 16 + g;
            int c = wn + nf * 8 + 2 * t4;
            size_t base = ((size_t)b * S_LEN) * DM + (size_t)h * DKH + c;
            *(float2*)&g_ctx[base + (size_t)r * DM] =
                make_float2(acc[mf][nf][0], acc[mf][nf][1]);
            *(float2*)&g_ctx[base + (size_t)(r + 8) * DM] =
                make_float2(acc[mf][nf][2], acc[mf][nf][3]);
        }
}

// ---------------------------------------------------------------------------
extern "C" void kernel_launch(void* const* d_in, const int* in_sizes, int n_in,
                              void* d_out, int out_size)
{
    const float* query = (const float*)d_in[0];
    const float* key_  = (const float*)d_in[1];
    const float* value = (const float*)d_in[2];
    const float* Wq = (const float*)d_in[3];
    const float* bq = (const float*)d_in[4];
    const float* Wk = (const float*)d_in[5];
    const float* bk = (const float*)d_in[6];
    const float* Wv = (const float*)d_in[7];
    const float* bv = (const float*)d_in[8];
    const float* Wo = (const float*)d_in[9];
    const float* bo = (const float*)d_in[10];

    float* out = (float*)d_out;                                  // [2,2048,1024]
    float* weights = out + (size_t)NB * S_LEN * DM;              // [2,16,2048,2048]

    dim3 blk(256);
    dim3 gProj(DM / 128, (NB * S_LEN) / 128);                    // (8, 32)
    proj_tc<0><<<gProj, blk>>>(query, Wq, bq, nullptr);
    proj_tc<1><<<gProj, blk>>>(key_,  Wk, bk, nullptr);
    proj_tc<2><<<gProj, blk>>>(value, Wv, bv, nullptr);

    dim3 gScore(S_LEN / 128, S_LEN / 128, BH);                   // (16, 16, 32)
    scores_tc<<<gScore, blk>>>(weights);

    softmax_kernel<<<BH * S_LEN, blk>>>(weights);                // 65536 rows

    dim3 gCtx(1, S_LEN / 128, BH);                               // (1, 16, 32)
    context_tc<<<gCtx, blk>>>(weights);

    proj_tc<3><<<gProj, blk>>>(nullptr, Wo, bo, out);
}

// round 5
// speedup vs baseline: 1.9296x; 1.0181x over previous
#include <cuda_runtime.h>
#include <cstdint>

#define S_LEN 2048
#define NB 2
#define DM 1024
#define NH 16
#define DKH 64
#define BH (NB * NH)

// ---------------------------------------------------------------------------
// Persistent pre-split scratch (allocation-free rule: __device__ globals)
// ---------------------------------------------------------------------------
__device__ uint32_t g_xh[3][NB * S_LEN * DM];   // query/key/value hi
__device__ uint32_t g_xl[3][NB * S_LEN * DM];   // lo
__device__ uint32_t g_wh[4][DM * DM];           // Wq/Wk/Wv/Wo hi
__device__ uint32_t g_wl[4][DM * DM];
__device__ uint32_t g_Qh[BH * S_LEN * DKH], g_Ql[BH * S_LEN * DKH];
__device__ uint32_t g_Kh[BH * S_LEN * DKH], g_Kl[BH * S_LEN * DKH];
__device__ uint32_t g_Vh[BH * S_LEN * DKH], g_Vl[BH * S_LEN * DKH];
__device__ uint32_t g_ctxh[NB * S_LEN * DM], g_ctxl[NB * S_LEN * DM];

// ---------------------------------------------------------------------------
// helpers
// ---------------------------------------------------------------------------
__device__ __forceinline__ uint32_t cvt_tf32(float x)
{
    uint32_t r;
    asm("cvt.rna.tf32.f32 %0, %1;" : "=r"(r) : "f"(x));
    return r;
}
__device__ __forceinline__ void split32(float x, uint32_t& hi, uint32_t& lo)
{
    hi = cvt_tf32(x);
    lo = cvt_tf32(x - __uint_as_float(hi));
}
__device__ __forceinline__ void mma8(float* c, const uint32_t* a,
                                     uint32_t b0, uint32_t b1)
{
    asm volatile(
        "mma.sync.aligned.m16n8k8.row.col.f32.tf32.tf32.f32 "
        "{%0,%1,%2,%3}, {%4,%5,%6,%7}, {%8,%9}, {%0,%1,%2,%3};"
        : "+f"(c[0]), "+f"(c[1]), "+f"(c[2]), "+f"(c[3])
        : "r"(a[0]), "r"(a[1]), "r"(a[2]), "r"(a[3]), "r"(b0), "r"(b1));
}
__device__ __forceinline__ void ldsm4(uint32_t* r, uint32_t addr)
{
    asm volatile(
        "ldmatrix.sync.aligned.m8n8.x4.shared.b16 {%0,%1,%2,%3}, [%4];"
        : "=r"(r[0]), "=r"(r[1]), "=r"(r[2]), "=r"(r[3]) : "r"(addr));
}
__device__ __forceinline__ void cpa16(uint32_t saddr, const void* g)
{
    asm volatile("cp.async.cg.shared.global [%0], [%1], 16;"
                 :: "r"(saddr), "l"(g));
}
#define CP_COMMIT asm volatile("cp.async.commit_group;")
#define CP_WAIT1  asm volatile("cp.async.wait_group 1;")

// ---------------------------------------------------------------------------
// Pre-split pass: fp32 -> (tf32 hi, tf32 lo).  TGT 0 = inputs, 1 = weights.
// ---------------------------------------------------------------------------
template <int TGT, int IDX>
__global__ __launch_bounds__(256) void split_k(const float4* __restrict__ src)
{
    const int n4 = (TGT == 0) ? (NB * S_LEN * DM / 4) : (DM * DM / 4);
    int i = blockIdx.x * 256 + threadIdx.x;
    if (i >= n4) return;
    float4 v = src[i];
    uint4 h, l;
    split32(v.x, h.x, l.x); split32(v.y, h.y, l.y);
    split32(v.z, h.z, l.z); split32(v.w, h.w, l.w);
    uint4* H = (uint4*)((TGT == 0) ? g_xh[IDX] : g_wh[IDX]);
    uint4* L = (uint4*)((TGT == 0) ? g_xl[IDX] : g_wl[IDX]);
    H[i] = h; L[i] = l;
}

// ---------------------------------------------------------------------------
// Projection GEMM (pre-split operands, 3xTF32, cp.async double buffer)
// BM=BN=128, BK=16, 512 threads, warp tile 32x32.
// MODE 0/1/2: A=g_x[MODE], B=g_w[MODE]; epilogue splits into g_{Q,K,V}h/l
//             (MODE 0 scales by 0.125 after bias)
// MODE 3:     A=g_ctx h/l, B=g_w[3]; epilogue +bias -> fp32 C
// smem (words): AH 2x2560 @0 | AL @5120 | BH 2x2176 @10240 | BL @14592
// ---------------------------------------------------------------------------
template <int MODE>
__global__ __launch_bounds__(512) void proj_tc(const float* __restrict__ bias,
                                               float* __restrict__ C)
{
    extern __shared__ uint32_t sm[];
    const uint32_t* Ah_ = (MODE == 3) ? g_ctxh : g_xh[MODE];
    const uint32_t* Al_ = (MODE == 3) ? g_ctxl : g_xl[MODE];
    const uint32_t* Bh_ = g_wh[MODE];
    const uint32_t* Bl_ = g_wl[MODE];
    uint32_t sbase = (uint32_t)__cvta_generic_to_shared(sm);

    int tid = threadIdx.x;
    int lane = tid & 31, warp = tid >> 5;
    int g = lane >> 2, t4 = lane & 3;
    int mat = lane >> 3, rl = lane & 7;
    int wm = (warp & 3) * 32, wn = (warp >> 2) * 32;
    int row0 = blockIdx.y * 128, col0 = blockIdx.x * 128;

    int rowA = wm + (mat & 1) * 8 + rl;
    int aSel = mat >> 1;
    int fr = tid >> 2, fc = (tid & 3) * 4;     // A fill: 128 rows x 4 chunks
    int br = tid >> 5, bc = (tid & 31) * 4;    // B fill: 16 rows x 32 chunks

    float acc[2][4][4] = {};

    auto fill = [&](int buf, int k0) {
        uint32_t da = sbase + (buf * 2560 + fr * 20 + fc) * 4;
        const uint32_t* ga = Ah_ + (size_t)(row0 + fr) * DM + k0 + fc;
        cpa16(da, ga);
        cpa16(da + 5120 * 4, Al_ + (size_t)(row0 + fr) * DM + k0 + fc);
        uint32_t db = sbase + (10240 + buf * 2176 + br * 136 + bc) * 4;
        cpa16(db, Bh_ + (size_t)(k0 + br) * DM + col0 + bc);
        cpa16(db + 4352 * 4, Bl_ + (size_t)(k0 + br) * DM + col0 + bc);
    };

    fill(0, 0);
    CP_COMMIT;
    int buf = 0;
    for (int k0 = 0; k0 < DM; k0 += 16) {
        if (k0 + 16 < DM) fill(buf ^ 1, k0 + 16);
        CP_COMMIT;
        CP_WAIT1;
        __syncthreads();
        const uint32_t* sBH = sm + 10240 + buf * 2176;
        const uint32_t* sBL = sBH + 4352;
        uint32_t aBh = sbase + (buf * 2560 + rowA * 20) * 4;
        uint32_t aBl = aBh + 5120 * 4;
#pragma unroll
        for (int ks = 0; ks < 2; ks++) {
            uint32_t ah[2][4], al[2][4];
            uint32_t co = (uint32_t)(ks * 2 + aSel) * 16;
#pragma unroll
            for (int mf = 0; mf < 2; mf++) {
                ldsm4(ah[mf], aBh + mf * 1280 + co);
                ldsm4(al[mf], aBl + mf * 1280 + co);
            }
#pragma unroll
            for (int nf = 0; nf < 4; nf++) {
                int bi = (ks * 8 + t4) * 136 + wn + nf * 8 + g;
                uint32_t bh0 = sBH[bi], bh1 = sBH[bi + 544];
                uint32_t bl0 = sBL[bi], bl1 = sBL[bi + 544];
#pragma unroll
                for (int mf = 0; mf < 2; mf++) {
                    mma8(acc[mf][nf], ah[mf], bh0, bh1);
                    mma8(acc[mf][nf], ah[mf], bl0, bl1);
                    mma8(acc[mf][nf], al[mf], bh0, bh1);
                }
            }
        }
        __syncthreads();
        buf ^= 1;
    }

#pragma unroll
    for (int mf = 0; mf < 2; mf++)
#pragma unroll
        for (int nf = 0; nf < 4; nf++) {
            int r = row0 + wm + mf * 16 + g;
            int c = col0 + wn + nf * 8 + 2 * t4;
            float b0 = bias[c], b1 = bias[c + 1];
            float v00 = acc[mf][nf][0] + b0, v01 = acc[mf][nf][1] + b1;
            float v10 = acc[mf][nf][2] + b0, v11 = acc[mf][nf][3] + b1;
            if (MODE == 3) {
                *(float2*)&C[(size_t)r * DM + c] = make_float2(v00, v01);
                *(float2*)&C[(size_t)(r + 8) * DM + c] = make_float2(v10, v11);
            } else {
                if (MODE == 0) {
                    v00 *= 0.125f; v01 *= 0.125f; v10 *= 0.125f; v11 *= 0.125f;
                }
                uint32_t* DH = (MODE == 0) ? g_Qh : (MODE == 1) ? g_Kh : g_Vh;
                uint32_t* DL = (MODE == 0) ? g_Ql : (MODE == 1) ? g_Kl : g_Vl;
                int hh = c >> 6, d = c & 63, b = r >> 11, s = r & 2047;
                size_t base = (((size_t)(b << 4) + hh) * S_LEN + s) * DKH + d;
                uint2 h2, l2;
                split32(v00, h2.x, l2.x); split32(v01, h2.y, l2.y);
                *(uint2*)&DH[base] = h2; *(uint2*)&DL[base] = l2;
                split32(v10, h2.x, l2.x); split32(v11, h2.y, l2.y);
                *(uint2*)&DH[base + 8 * DKH] = h2; *(uint2*)&DL[base + 8 * DKH] = l2;
            }
        }
}

// ---------------------------------------------------------------------------
// scores[bh] = Qh @ Kh^T (Q pre-scaled). Pre-split Q/K, both via ldmatrix.
// BM=BN=128, BK=16 (4 iters), 512 threads, warp tile 32x32.
// smem words: QH 2x2560 @0 | QL @5120 | KH @10240 | KL @15360
// ---------------------------------------------------------------------------
__global__ __launch_bounds__(512) void scores_tc(float* __restrict__ W)
{
    extern __shared__ uint32_t sm[];
    int bh = blockIdx.z;
    size_t off = (size_t)bh * S_LEN * DKH;
    const uint32_t* Qh_ = g_Qh + off; const uint32_t* Ql_ = g_Ql + off;
    const uint32_t* Kh_ = g_Kh + off; const uint32_t* Kl_ = g_Kl + off;
    float* Wh = W + (size_t)bh * S_LEN * S_LEN;
    uint32_t sbase = (uint32_t)__cvta_generic_to_shared(sm);

    int tid = threadIdx.x;
    int lane = tid & 31, warp = tid >> 5;
    int g = lane >> 2, t4 = lane & 3;
    int mat = lane >> 3, rl = lane & 7;
    int wm = (warp & 3) * 32, wn = (warp >> 2) * 32;
    int row0 = blockIdx.y * 128, col0 = blockIdx.x * 128;

    int rowA = wm + (mat & 1) * 8 + rl;
    int aSel = mat >> 1;
    int rowB = wn + (mat >> 1) * 8 + rl;
    int bSel = mat & 1;
    int fr = tid >> 2, fc = (tid & 3) * 4;

    float acc[2][4][4] = {};

    auto fill = [&](int buf, int k0) {
        uint32_t da = sbase + (buf * 2560 + fr * 20 + fc) * 4;
        cpa16(da,             Qh_ + (size_t)(row0 + fr) * DKH + k0 + fc);
        cpa16(da + 5120 * 4,  Ql_ + (size_t)(row0 + fr) * DKH + k0 + fc);
        cpa16(da + 10240 * 4, Kh_ + (size_t)(col0 + fr) * DKH + k0 + fc);
        cpa16(da + 15360 * 4, Kl_ + (size_t)(col0 + fr) * DKH + k0 + fc);
    };

    fill(0, 0);
    CP_COMMIT;
    int buf = 0;
#pragma unroll
    for (int k0 = 0; k0 < DKH; k0 += 16) {
        if (k0 + 16 < DKH) fill(buf ^ 1, k0 + 16);
        CP_COMMIT;
        CP_WAIT1;
        __syncthreads();
        uint32_t aBh = sbase + (buf * 2560 + rowA * 20) * 4;
        uint32_t aBl = aBh + 5120 * 4;
        uint32_t bBh = sbase + (buf * 2560 + rowB * 20) * 4 + 10240 * 4;
        uint32_t bBl = bBh + 5120 * 4;
#pragma unroll
        for (int ks = 0; ks < 2; ks++) {
            uint32_t ah[2][4], al[2][4], bh[2][4], bl[2][4];
            uint32_t ca = (uint32_t)(ks * 2 + aSel) * 16;
            uint32_t cb = (uint32_t)(ks * 2 + bSel) * 16;
#pragma unroll
            for (int mf = 0; mf < 2; mf++) {
                ldsm4(ah[mf], aBh + mf * 1280 + ca);
                ldsm4(al[mf], aBl + mf * 1280 + ca);
            }
#pragma unroll
            for (int p = 0; p < 2; p++) {
                ldsm4(bh[p], bBh + p * 1280 + cb);
                ldsm4(bl[p], bBl + p * 1280 + cb);
            }
#pragma unroll
            for (int mf = 0; mf < 2; mf++)
#pragma unroll
                for (int nf = 0; nf < 4; nf++) {
                    int p = nf >> 1, o = (nf & 1) * 2;
                    mma8(acc[mf][nf], ah[mf], bh[p][o], bh[p][o + 1]);
                    mma8(acc[mf][nf], ah[mf], bl[p][o], bl[p][o + 1]);
                    mma8(acc[mf][nf], al[mf], bh[p][o], bh[p][o + 1]);
                }
        }
        __syncthreads();
        buf ^= 1;
    }

#pragma unroll
    for (int mf = 0; mf < 2; mf++)
#pragma unroll
        for (int nf = 0; nf < 4; nf++) {
            int r = row0 + wm + mf * 16 + g;
            int c = col0 + wn + nf * 8 + 2 * t4;
            *(float2*)&Wh[(size_t)r * S_LEN + c] =
                make_float2(acc[mf][nf][0], acc[mf][nf][1]);
            *(float2*)&Wh[(size_t)(r + 8) * S_LEN + c] =
                make_float2(acc[mf][nf][2], acc[mf][nf][3]);
        }
}

// ---------------------------------------------------------------------------
// In-place row softmax over 2048 cols. One block (256 thr) per row.
// ---------------------------------------------------------------------------
__global__ __launch_bounds__(256) void softmax_kernel(float* __restrict__ W)
{
    __shared__ float red[256];
    float4* p = (float4*)(W + (size_t)blockIdx.x * S_LEN);
    int tid = threadIdx.x;
    float4 v0 = p[tid], v1 = p[tid + 256];
    float m = fmaxf(fmaxf(fmaxf(v0.x, v0.y), fmaxf(v0.z, v0.w)),
                    fmaxf(fmaxf(v1.x, v1.y), fmaxf(v1.z, v1.w)));
    red[tid] = m;
    __syncthreads();
    for (int s = 128; s > 0; s >>= 1) {
        if (tid < s) red[tid] = fmaxf(red[tid], red[tid + s]);
        __syncthreads();
    }
    m = red[0];
    __syncthreads();
    v0.x = __expf(v0.x - m); v0.y = __expf(v0.y - m);
    v0.z = __expf(v0.z - m); v0.w = __expf(v0.w - m);
    v1.x = __expf(v1.x - m); v1.y = __expf(v1.y - m);
    v1.z = __expf(v1.z - m); v1.w = __expf(v1.w - m);
    red[tid] = (v0.x + v0.y + v0.z + v0.w) + (v1.x + v1.y + v1.z + v1.w);
    __syncthreads();
    for (int s = 128; s > 0; s >>= 1) {
        if (tid < s) red[tid] += red[tid + s];
        __syncthreads();
    }
    float inv = 1.0f / red[0];
    v0.x *= inv; v0.y *= inv; v0.z *= inv; v0.w *= inv;
    v1.x *= inv; v1.y *= inv; v1.z *= inv; v1.w *= inv;
    p[tid] = v0; p[tid + 256] = v1;
}

// ---------------------------------------------------------------------------
// context[bh] = W_h @ V_h -> split into g_ctx h/l.
// A = W raw fp32 (tf32-rounded in reg, single term), B = pre-split V (2 terms).
// BM=128, BN=64, BK=16 (128 iters), 512 threads, warp tile 32x16.
// ---------------------------------------------------------------------------
__global__ __launch_bounds__(512) void context_tc(const float* __restrict__ W)
{
    __shared__ float    sA[2][128 * 20];
    __shared__ uint32_t sVH[2][16 * 72], sVL[2][16 * 72];
    int bh = blockIdx.z;
    const float* Wh = W + (size_t)bh * S_LEN * S_LEN;
    const uint32_t* Vh_ = g_Vh + (size_t)bh * S_LEN * DKH;
    const uint32_t* Vl_ = g_Vl + (size_t)bh * S_LEN * DKH;
    int b = bh >> 4, h = bh & 15;
    uint32_t sbase = (uint32_t)__cvta_generic_to_shared(sA);

    int tid = threadIdx.x;
    int lane = tid & 31, warp = tid >> 5;
    int g = lane >> 2, t4 = lane & 3;
    int mat = lane >> 3, rl = lane & 7;
    int wm = (warp & 3) * 32, wn = (warp >> 2) * 16;
    int row0 = blockIdx.y * 128;

    int rowA = wm + (mat & 1) * 8 + rl;
    int aSel = mat >> 1;
    int fr = tid >> 2, fc = (tid & 3) * 4;
    int vr = tid >> 4, vc = (tid & 15) * 4;

    float acc[2][2][4] = {};

    auto fill = [&](int buf, int k0) {
        cpa16((uint32_t)__cvta_generic_to_shared(&sA[buf][fr * 20 + fc]),
              Wh + (size_t)(row0 + fr) * S_LEN + k0 + fc);
        if (tid < 256) {
            cpa16((uint32_t)__cvta_generic_to_shared(&sVH[buf][vr * 72 + vc]),
                  Vh_ + (size_t)(k0 + vr) * DKH + vc);
            cpa16((uint32_t)__cvta_generic_to_shared(&sVL[buf][vr * 72 + vc]),
                  Vl_ + (size_t)(k0 + vr) * DKH + vc);
        }
    };

    fill(0, 0);
    CP_COMMIT;
    int buf = 0;
    for (int k0 = 0; k0 < S_LEN; k0 += 16) {
        if (k0 + 16 < S_LEN) fill(buf ^ 1, k0 + 16);
        CP_COMMIT;
        CP_WAIT1;
        __syncthreads();
        uint32_t aB = sbase + (buf * 2560 + rowA * 20) * 4;
        const uint32_t* VH = sVH[buf];
        const uint32_t* VL = sVL[buf];
#pragma unroll
        for (int ks = 0; ks < 2; ks++) {
            uint32_t fa[2][4], ah[2][4];
            uint32_t co = (uint32_t)(ks * 2 + aSel) * 16;
#pragma unroll
            for (int mf = 0; mf < 2; mf++) {
                ldsm4(fa[mf], aB + mf * 1280 + co);
#pragma unroll
                for (int j = 0; j < 4; j++)
                    ah[mf][j] = cvt_tf32(__uint_as_float(fa[mf][j]));
            }
#pragma unroll
            for (int nf = 0; nf < 2; nf++) {
                int bi = (ks * 8 + t4) * 72 + wn + nf * 8 + g;
                uint32_t bh0 = VH[bi], bh1 = VH[bi + 288];
                uint32_t bl0 = VL[bi], bl1 = VL[bi + 288];
#pragma unroll
                for (int mf = 0; mf < 2; mf++) {
                    mma8(acc[mf][nf], ah[mf], bh0, bh1);
                    mma8(acc[mf][nf], ah[mf], bl0, bl1);
                }
            }
        }
        __syncthreads();
        buf ^= 1;
    }

#pragma unroll
    for (int mf = 0; mf < 2; mf++)
#pragma unroll
        for (int nf = 0; nf < 2; nf++) {
            int r = row0 + wm + mf * 16 + g;
            int c = wn + nf * 8 + 2 * t4;
            size_t base = ((size_t)b * S_LEN + r) * DM + (size_t)h * DKH + c;
            uint2 h2, l2;
            split32(acc[mf][nf][0], h2.x, l2.x);
            split32(acc[mf][nf][1], h2.y, l2.y);
            *(uint2*)&g_ctxh[base] = h2; *(uint2*)&g_ctxl[base] = l2;
            split32(acc[mf][nf][2], h2.x, l2.x);
            split32(acc[mf][nf][3], h2.y, l2.y);
            *(uint2*)&g_ctxh[base + 8 * DM] = h2;
            *(uint2*)&g_ctxl[base + 8 * DM] = l2;
        }
}

// ---------------------------------------------------------------------------
extern "C" void kernel_launch(void* const* d_in, const int* in_sizes, int n_in,
                              void* d_out, int out_size)
{
    const float* query = (const float*)d_in[0];
    const float* key_  = (const float*)d_in[1];
    const float* value = (const float*)d_in[2];
    const float* bq = (const float*)d_in[4];
    const float* bk = (const float*)d_in[6];
    const float* bv = (const float*)d_in[8];
    const float* bo = (const float*)d_in[10];

    float* out = (float*)d_out;                       // [2,2048,1024]
    float* weights = out + (size_t)NB * S_LEN * DM;   // [2,16,2048,2048]

    const int PROJ_SMEM = 18944 * 4;    // 75776 B
    const int SCORE_SMEM = 20480 * 4;   // 81920 B
    cudaFuncSetAttribute(proj_tc<0>, cudaFuncAttributeMaxDynamicSharedMemorySize, PROJ_SMEM);
    cudaFuncSetAttribute(proj_tc<1>, cudaFuncAttributeMaxDynamicSharedMemorySize, PROJ_SMEM);
    cudaFuncSetAttribute(proj_tc<2>, cudaFuncAttributeMaxDynamicSharedMemorySize, PROJ_SMEM);
    cudaFuncSetAttribute(proj_tc<3>, cudaFuncAttributeMaxDynamicSharedMemorySize, PROJ_SMEM);
    cudaFuncSetAttribute(scores_tc, cudaFuncAttributeMaxDynamicSharedMemorySize, SCORE_SMEM);

    // Pre-split inputs & weights
    split_k<0, 0><<<4096, 256>>>((const float4*)query);
    split_k<0, 1><<<4096, 256>>>((const float4*)key_);
    split_k<0, 2><<<4096, 256>>>((const float4*)value);
    split_k<1, 0><<<1024, 256>>>((const float4*)d_in[3]);
    split_k<1, 1><<<1024, 256>>>((const float4*)d_in[5]);
    split_k<1, 2><<<1024, 256>>>((const float4*)d_in[7]);
    split_k<1, 3><<<1024, 256>>>((const float4*)d_in[9]);

    dim3 blk(512);
    dim3 gProj(DM / 128, (NB * S_LEN) / 128);         // (8, 32)
    proj_tc<0><<<gProj, blk, PROJ_SMEM>>>(bq, nullptr);
    proj_tc<1><<<gProj, blk, PROJ_SMEM>>>(bk, nullptr);
    proj_tc<2><<<gProj, blk, PROJ_SMEM>>>(bv, nullptr);

    dim3 gScore(S_LEN / 128, S_LEN / 128, BH);        // (16, 16, 32)
    scores_tc<<<gScore, blk, SCORE_SMEM>>>(weights);

    softmax_kernel<<<BH * S_LEN, 256>>>(weights);

    dim3 gCtx(1, S_LEN / 128, BH);                    // (1, 16, 32)
    context_tc<<<gCtx, blk>>>(weights);

    proj_tc<3><<<gProj, blk, PROJ_SMEM>>>(bo, out);
}